// round 14
// baseline (speedup 1.0000x reference)
#include <cuda_runtime.h>
#include <cuda_fp16.h>
#include <cstdint>

// ---------------------------------------------------------------------------
// GAT layer (sm_100 base target — legacy mma.sync only):
//   k1: H = X @ W                      (tf32 mma.sync m16n8k8, 27us)
//   k2: as/an row dots (fp32); emit g_h16 = fp16 H in k-paired layout
//   k3: Out = elu( (P @ H) / rowsum(P) )  via fp16 mma.sync m16n8k16
//       fp16 tile acc -> fp32 masters. 32x256 per CTA, JT=64, grid 256,
//       2 CTAs/SM. R11 structure (computeP overlapped inside mma stream)
//       + DISTANCE-2 register prefetch of M/adj (two parity sets).
// ---------------------------------------------------------------------------

#define NROWS 8192
#define IND   512
#define OUTD  256
#define JT    64
#define NTILE (NROWS / JT)     // 128

__device__ __align__(16) float  g_h  [NROWS * OUTD];
__device__ __align__(16) __half g_h16[NROWS * OUTD];   // word[jpair*256+n] = {h[2j][n], h[2j+1][n]}
__device__ __align__(16) float  g_as [NROWS];
__device__ __align__(16) float  g_an [NROWS];

#define PSCALE 0.015625f   // 2^-6

// ---------------------------------------------------------------------------
__device__ __forceinline__ float to_tf32(float x) {
    unsigned r;
    asm("cvt.rna.tf32.f32 %0, %1;\n" : "=r"(r) : "f"(x));
    return __uint_as_float(r);
}
__device__ __forceinline__ void mma_tf32(float* d, const unsigned* a,
                                         unsigned b0, unsigned b1) {
    asm volatile(
        "mma.sync.aligned.m16n8k8.row.col.f32.tf32.tf32.f32 "
        "{%0,%1,%2,%3}, {%4,%5,%6,%7}, {%8,%9}, {%0,%1,%2,%3};\n"
        : "+f"(d[0]), "+f"(d[1]), "+f"(d[2]), "+f"(d[3])
        : "r"(a[0]), "r"(a[1]), "r"(a[2]), "r"(a[3]), "r"(b0), "r"(b1));
}
__device__ __forceinline__ void mma_f16a(unsigned* d, const unsigned* a,
                                         unsigned b0, unsigned b1) {
    asm volatile(
        "mma.sync.aligned.m16n8k16.row.col.f16.f16.f16.f16 "
        "{%0,%1}, {%2,%3,%4,%5}, {%6,%7}, {%0,%1};\n"
        : "+r"(d[0]), "+r"(d[1])
        : "r"(a[0]), "r"(a[1]), "r"(a[2]), "r"(a[3]), "r"(b0), "r"(b1));
}
__device__ __forceinline__ void ldsm4(unsigned* a, unsigned addr) {
    asm volatile(
        "ldmatrix.sync.aligned.m8n8.x4.shared.b16 {%0,%1,%2,%3}, [%4];\n"
        : "=r"(a[0]), "=r"(a[1]), "=r"(a[2]), "=r"(a[3]) : "r"(addr));
}
__device__ __forceinline__ void cp16(void* smem, const void* g) {
    unsigned s = (unsigned)__cvta_generic_to_shared(smem);
    asm volatile("cp.async.cg.shared.global [%0], [%1], 16;\n" :: "r"(s), "l"(g));
}
__device__ __forceinline__ float elu_f(float x) { return x > 0.f ? x : expm1f(x); }

// ---------------------------------------------------------------------------
// Kernel 1: H = X @ W, tf32 mma.sync (R6-proven, 27us). grid (2, 64).
// ---------------------------------------------------------------------------
#define K1_SMEM_BYTES ((2 * 128 * 36 + 2 * 32 * 136) * 4)

__global__ __launch_bounds__(256) void k1_gemm_xw(const float* __restrict__ X,
                                                  const float* __restrict__ W) {
    extern __shared__ float sm1[];
    float* sX = sm1;
    float* sW = sm1 + 2 * 128 * 36;

    const int tid = threadIdx.x;
    const int lane = tid & 31, warp = tid >> 5;
    const int wr = warp & 3, wc = warp >> 2;
    const int m0 = blockIdx.y * 128, n0 = blockIdx.x * 128;
    const int r0 = lane >> 2, c0 = lane & 3;
    const int sel = lane >> 3, mrow = lane & 7;
    const int lrow = ((sel & 1) << 3) + mrow, lcol = (sel >> 1) << 2;
    const unsigned sX_u = (unsigned)__cvta_generic_to_shared(sX);

    float acc[2][8][4] = {};
    float4 xv[4], wv[4];

    auto ldg_stage = [&](int k0) {
#pragma unroll
        for (int p = 0; p < 4; p++) {
            int q = tid + p * 256;
            xv[p] = *(const float4*)&X[(size_t)(m0 + (q >> 3)) * IND + k0 + ((q & 7) << 2)];
            wv[p] = *(const float4*)&W[(size_t)(k0 + (q >> 5)) * OUTD + n0 + ((q & 31) << 2)];
        }
    };
    auto sts_stage = [&](int buf) {
#pragma unroll
        for (int p = 0; p < 4; p++) {
            int q = tid + p * 256;
            float4 t = make_float4(to_tf32(xv[p].x), to_tf32(xv[p].y),
                                   to_tf32(xv[p].z), to_tf32(xv[p].w));
            *(float4*)&sX[buf * 4608 + (q >> 3) * 36 + ((q & 7) << 2)] = t;
            float4 u = make_float4(to_tf32(wv[p].x), to_tf32(wv[p].y),
                                   to_tf32(wv[p].z), to_tf32(wv[p].w));
            *(float4*)&sW[buf * 4352 + (q >> 5) * 136 + ((q & 31) << 2)] = u;
        }
    };

    ldg_stage(0);
    sts_stage(0);
    __syncthreads();

    for (int s = 0; s < 16; s++) {
        const int buf = s & 1;
        if (s < 15) ldg_stage((s + 1) * 32);
#pragma unroll
        for (int k8 = 0; k8 < 4; k8++) {
            const int kb = k8 << 3;
            unsigned afr[2][4];
#pragma unroll
            for (int mt = 0; mt < 2; mt++) {
                unsigned addr = sX_u +
                    (buf * 4608 + (wr * 32 + mt * 16 + lrow) * 36 + kb + lcol) * 4u;
                ldsm4(afr[mt], addr);
            }
            const float* wp = &sW[buf * 4352 + (kb + c0) * 136 + wc * 64 + r0];
#pragma unroll
            for (int nt = 0; nt < 8; nt++) {
                unsigned b0 = __float_as_uint(wp[nt * 8]);
                unsigned b1 = __float_as_uint(wp[4 * 136 + nt * 8]);
#pragma unroll
                for (int mt = 0; mt < 2; mt++)
                    mma_tf32(acc[mt][nt], afr[mt], b0, b1);
            }
        }
        if (s < 15) {
            __syncthreads();
            sts_stage((s + 1) & 1);
            __syncthreads();
        }
    }
#pragma unroll
    for (int mt = 0; mt < 2; mt++)
#pragma unroll
        for (int nt = 0; nt < 8; nt++) {
            const int ra = wr * 32 + mt * 16 + r0;
            const int cb = wc * 64 + nt * 8 + c0 * 2;
            *(float2*)&g_h[(size_t)(m0 + ra) * OUTD + n0 + cb] =
                make_float2(acc[mt][nt][0], acc[mt][nt][1]);
            *(float2*)&g_h[(size_t)(m0 + ra + 8) * OUTD + n0 + cb] =
                make_float2(acc[mt][nt][2], acc[mt][nt][3]);
        }
}

// ---------------------------------------------------------------------------
// Kernel 2: as/an row dots (fp32); write g_h16 (fp16, k-paired layout).
// ---------------------------------------------------------------------------
__global__ __launch_bounds__(256) void k2_attvec(const float* __restrict__ a_self,
                                                 const float* __restrict__ a_neighs) {
    const int warp = threadIdx.x >> 5, lane = threadIdx.x & 31;
    const int row = blockIdx.x * 8 + warp;
    const float4* h4 = (const float4*)&g_h[(size_t)row * OUTD];
    __half* dst = &g_h16[(size_t)(row >> 1) * 512 + (row & 1)];
    float s1 = 0.f, s2 = 0.f;
#pragma unroll
    for (int q = 0; q < 2; q++) {
        float4 v = h4[lane + 32 * q];
        float4 a = ((const float4*)a_self)[lane + 32 * q];
        float4 b = ((const float4*)a_neighs)[lane + 32 * q];
        s1 += v.x * a.x + v.y * a.y + v.z * a.z + v.w * a.w;
        s2 += v.x * b.x + v.y * b.y + v.z * b.z + v.w * b.w;
        const int c = (lane + 32 * q) * 4;
        dst[(c + 0) * 2] = __float2half_rn(v.x);
        dst[(c + 1) * 2] = __float2half_rn(v.y);
        dst[(c + 2) * 2] = __float2half_rn(v.z);
        dst[(c + 3) * 2] = __float2half_rn(v.w);
    }
#pragma unroll
    for (int off = 16; off >= 1; off >>= 1) {
        s1 += __shfl_xor_sync(0xffffffffu, s1, off);
        s2 += __shfl_xor_sync(0xffffffffu, s2, off);
    }
    if (lane == 0) { g_as[row] = s1; g_an[row] = s2; }
}

// ---------------------------------------------------------------------------
// Kernel 3: fused masked-exp attention GEMM, fp16 m16n8k16 fp16-acc.
// 32 rows x 256 cols per CTA, 128 k-tiles of 64 j. grid 256, 256 thr.
// smem ~76KB -> 2 CTAs/SM. M/adj prefetched to registers at DISTANCE 2.
// ---------------------------------------------------------------------------
#define SHU_STRIDE 260
#define SHU_BUF    (32 * SHU_STRIDE)          // u32 per buffer
#define SP_STRIDE  72                         // halves per row
#define SP_HBUF    (32 * SP_STRIDE)           // halves per buffer
#define SP_BYTE0   (2 * SHU_BUF * 4)          // 66560
#define SAS_F      ((SP_BYTE0 + 2 * SP_HBUF * 2) / 4)   // float idx 18944
#define SRS_F      (SAS_F + 32)
#define K3_SMEM_BYTES ((SRS_F + 32) * 4)      // 76032

__global__ __launch_bounds__(256, 2) void k3_attn(const float* __restrict__ Adj,
                                                  const float* __restrict__ Mg,
                                                  float* __restrict__ Out) {
    extern __shared__ float sm[];
    uint32_t* sHu = (uint32_t*)sm;
    __half*   sPh = (__half*)((char*)sm + SP_BYTE0);
    float* s_as = sm + SAS_F;
    float* s_rs = sm + SRS_F;

    const int tid = threadIdx.x;
    const int lane = tid & 31, warp = tid >> 5;
    const int rowbase = blockIdx.x * 32;
    const int r0 = lane >> 2, c0 = lane & 3;
    const int g = tid >> 3, cbase = (tid & 7) << 3;   // row g, 8 cols per thread
    const unsigned sP_u = (unsigned)__cvta_generic_to_shared(sPh);

    if (tid < 8)
        *(float4*)&s_as[tid * 4] = *(const float4*)&g_as[rowbase + tid * 4];

    auto stageH = [&](int tt) {
        const int b = tt & 1;
        const char* src = (const char*)g_h16 + (size_t)tt * 32 * 1024;
#pragma unroll
        for (int p = 0; p < 8; p++) {
            int ch = tid + p * 256;
            int pr = ch >> 6, c = ch & 63;
            cp16(&sHu[b * SHU_BUF + pr * SHU_STRIDE + c * 4],
                 src + (size_t)pr * 1024 + c * 16);
        }
        asm volatile("cp.async.commit_group;\n" ::: "memory");
    };

    // M/adj prefetch: two parity-indexed register sets, distance 2.
    float4 mreg[2][2], areg[2][2];
    auto ldgMA = [&](int tt) {
        const int s = tt & 1;
        const size_t goff = (size_t)(rowbase + g) * NROWS + tt * JT + cbase;
        mreg[s][0] = __ldg((const float4*)&Mg[goff]);
        mreg[s][1] = __ldg((const float4*)&Mg[goff + 4]);
        areg[s][0] = __ldg((const float4*)&Adj[goff]);
        areg[s][1] = __ldg((const float4*)&Adj[goff + 4]);
    };

    float rsum = 0.f;

    auto computeP = [&](int tt) {
        const int b = tt & 1;
        const float asr = s_as[g];
        const int jb = tt * JT;
        float p[8];
#pragma unroll
        for (int hh = 0; hh < 2; hh++) {
            float4 m4 = mreg[b][hh], a4 = areg[b][hh];
            float4 an = *(const float4*)&g_an[jb + cbase + hh * 4];  // L1/L2-hot
            float t0 = (asr + an.x) * m4.x; t0 = t0 > 0.f ? t0 : 0.2f * t0;
            float t1 = (asr + an.y) * m4.y; t1 = t1 > 0.f ? t1 : 0.2f * t1;
            float t2 = (asr + an.z) * m4.z; t2 = t2 > 0.f ? t2 : 0.2f * t2;
            float t3 = (asr + an.w) * m4.w; t3 = t3 > 0.f ? t3 : 0.2f * t3;
            p[hh * 4 + 0] = a4.x > 0.f ? __expf(t0) : 0.f;
            p[hh * 4 + 1] = a4.y > 0.f ? __expf(t1) : 0.f;
            p[hh * 4 + 2] = a4.z > 0.f ? __expf(t2) : 0.f;
            p[hh * 4 + 3] = a4.w > 0.f ? __expf(t3) : 0.f;
        }
        rsum += ((p[0] + p[1]) + (p[2] + p[3])) +
                ((p[4] + p[5]) + (p[6] + p[7]));
        __half2 h01 = __floats2half2_rn(p[0] * PSCALE, p[1] * PSCALE);
        __half2 h23 = __floats2half2_rn(p[2] * PSCALE, p[3] * PSCALE);
        __half2 h45 = __floats2half2_rn(p[4] * PSCALE, p[5] * PSCALE);
        __half2 h67 = __floats2half2_rn(p[6] * PSCALE, p[7] * PSCALE);
        *(uint4*)&sPh[b * SP_HBUF + g * SP_STRIDE + cbase] =
            make_uint4(*(unsigned*)&h01, *(unsigned*)&h23,
                       *(unsigned*)&h45, *(unsigned*)&h67);
    };

    float acc[2][4][4] = {};   // fp32 masters

    // ---- prologue ----
    stageH(0);
    ldgMA(0);
    __syncthreads();                 // s_as visible
    computeP(0);                     // consumes set 0, writes sPh[0]
    ldgMA(1);                        // set 1, consumed mid-iter-0
    asm volatile("cp.async.wait_group 0;\n" ::: "memory");
    __syncthreads();

    // ---- main loop: 128 iterations ----
    for (int t = 0; t < NTILE; t++) {
        const int b = t & 1;
        const bool more = (t < NTILE - 1);
        if (more) stageH(t + 1);
        if (t + 2 < NTILE) ldgMA(t + 2);   // set[t&1], free since computeP(t)

        unsigned hacc[2][4][2] = {};   // fp16 tile accumulators
        {
            const int nb = warp * 32 + r0;
#pragma unroll
            for (int c16 = 0; c16 < 4; c16++) {
                unsigned afr[2][4];
#pragma unroll
                for (int mt = 0; mt < 2; mt++) {
                    unsigned addr = sP_u +
                        (b * SP_HBUF + (mt * 16 + (lane & 15)) * SP_STRIDE +
                         c16 * 16 + (lane >> 4) * 8) * 2u;
                    ldsm4(afr[mt], addr);
                }
                const uint32_t* hp =
                    &sHu[b * SHU_BUF + (c16 * 8 + c0) * SHU_STRIDE + nb];
#pragma unroll
                for (int nt = 0; nt < 4; nt++) {
                    unsigned b0 = hp[nt * 8];
                    unsigned b1 = hp[4 * SHU_STRIDE + nt * 8];
#pragma unroll
                    for (int mt = 0; mt < 2; mt++)
                        mma_f16a(hacc[mt][nt], afr[mt], b0, b1);
                }
                if (c16 == 1 && more) computeP(t + 1);  // overlap exp with HMMA
            }
        }

        // promote fp16 tile accumulators into fp32 masters
#pragma unroll
        for (int mt = 0; mt < 2; mt++)
#pragma unroll
            for (int nt = 0; nt < 4; nt++) {
                float2 lo = __half22float2(*(__half2*)&hacc[mt][nt][0]);
                float2 hi = __half22float2(*(__half2*)&hacc[mt][nt][1]);
                acc[mt][nt][0] += lo.x; acc[mt][nt][1] += lo.y;
                acc[mt][nt][2] += hi.x; acc[mt][nt][3] += hi.y;
            }

        asm volatile("cp.async.wait_group 0;\n" ::: "memory");
        __syncthreads();
    }

    // ---- rowsum reduction (8 threads per row, same warp) ----
#pragma unroll
    for (int off = 4; off >= 1; off >>= 1)
        rsum += __shfl_xor_sync(0xffffffffu, rsum, off);
    if ((tid & 7) == 0) s_rs[g] = rsum;
    __syncthreads();

    // ---- epilogue: divide (undo 2^-6 scale), elu, store ----
#pragma unroll
    for (int mt = 0; mt < 2; mt++) {
        const int ra = mt * 16 + r0;
        const float ia = 64.0f / s_rs[ra];
        const float ib = 64.0f / s_rs[ra + 8];
#pragma unroll
        for (int nt = 0; nt < 4; nt++) {
            const int col = warp * 32 + nt * 8 + c0 * 2;
            float2 va = make_float2(elu_f(acc[mt][nt][0] * ia),
                                    elu_f(acc[mt][nt][1] * ia));
            float2 vb = make_float2(elu_f(acc[mt][nt][2] * ib),
                                    elu_f(acc[mt][nt][3] * ib));
            *(float2*)&Out[(size_t)(rowbase + ra) * OUTD + col] = va;
            *(float2*)&Out[(size_t)(rowbase + ra + 8) * OUTD + col] = vb;
        }
    }
}

// ---------------------------------------------------------------------------
extern "C" void kernel_launch(void* const* d_in, const int* in_sizes, int n_in,
                              void* d_out, int out_size) {
    const float* X        = (const float*)d_in[0];
    const float* Adj      = (const float*)d_in[1];
    const float* Mg       = (const float*)d_in[2];
    const float* W        = (const float*)d_in[3];
    const float* a_self   = (const float*)d_in[4];
    const float* a_neighs = (const float*)d_in[5];
    float* Out = (float*)d_out;

    cudaFuncSetAttribute(k1_gemm_xw, cudaFuncAttributeMaxDynamicSharedMemorySize,
                         K1_SMEM_BYTES);
    cudaFuncSetAttribute(k3_attn, cudaFuncAttributeMaxDynamicSharedMemorySize,
                         K3_SMEM_BYTES);

    k1_gemm_xw<<<dim3(2, 64), 256, K1_SMEM_BYTES>>>(X, W);
    k2_attvec<<<1024, 256>>>(a_self, a_neighs);
    k3_attn<<<256, 256, K3_SMEM_BYTES>>>(Adj, Mg, Out);
}

// round 15
// speedup vs baseline: 1.4380x; 1.4380x over previous
#include <cuda_runtime.h>
#include <cuda_fp16.h>
#include <cstdint>

// ---------------------------------------------------------------------------
// GAT layer (sm_100 base target — legacy mma.sync only):
//   k1: H = X @ W                      (tf32 mma.sync m16n8k8, 27us)
//   k2: as/an row dots (fp32); emit g_h16 = fp16 H in k-paired layout
//   k3: Out = elu( (P @ H) / rowsum(P) )  via fp16 mma.sync m16n8k16
//       fp16 tile accumulate -> fp32 masters. 32 rows x 256 cols per CTA,
//       JT=64, grid 256, 2 CTAs/SM. R11 structure; computeP moved to the
//       LAST mma chunk (c16==3) to stretch M/adj LDG->use distance at zero
//       register cost (R14's 2-set prefetch spilled; this doesn't).
// ---------------------------------------------------------------------------

#define NROWS 8192
#define IND   512
#define OUTD  256
#define JT    64
#define NTILE (NROWS / JT)     // 128

__device__ __align__(16) float  g_h  [NROWS * OUTD];
__device__ __align__(16) __half g_h16[NROWS * OUTD];   // word[jpair*256+n] = {h[2j][n], h[2j+1][n]}
__device__ __align__(16) float  g_as [NROWS];
__device__ __align__(16) float  g_an [NROWS];

#define PSCALE 0.015625f   // 2^-6

// ---------------------------------------------------------------------------
__device__ __forceinline__ float to_tf32(float x) {
    unsigned r;
    asm("cvt.rna.tf32.f32 %0, %1;\n" : "=r"(r) : "f"(x));
    return __uint_as_float(r);
}
__device__ __forceinline__ void mma_tf32(float* d, const unsigned* a,
                                         unsigned b0, unsigned b1) {
    asm volatile(
        "mma.sync.aligned.m16n8k8.row.col.f32.tf32.tf32.f32 "
        "{%0,%1,%2,%3}, {%4,%5,%6,%7}, {%8,%9}, {%0,%1,%2,%3};\n"
        : "+f"(d[0]), "+f"(d[1]), "+f"(d[2]), "+f"(d[3])
        : "r"(a[0]), "r"(a[1]), "r"(a[2]), "r"(a[3]), "r"(b0), "r"(b1));
}
__device__ __forceinline__ void mma_f16a(unsigned* d, const unsigned* a,
                                         unsigned b0, unsigned b1) {
    asm volatile(
        "mma.sync.aligned.m16n8k16.row.col.f16.f16.f16.f16 "
        "{%0,%1}, {%2,%3,%4,%5}, {%6,%7}, {%0,%1};\n"
        : "+r"(d[0]), "+r"(d[1])
        : "r"(a[0]), "r"(a[1]), "r"(a[2]), "r"(a[3]), "r"(b0), "r"(b1));
}
__device__ __forceinline__ void ldsm4(unsigned* a, unsigned addr) {
    asm volatile(
        "ldmatrix.sync.aligned.m8n8.x4.shared.b16 {%0,%1,%2,%3}, [%4];\n"
        : "=r"(a[0]), "=r"(a[1]), "=r"(a[2]), "=r"(a[3]) : "r"(addr));
}
__device__ __forceinline__ void cp16(void* smem, const void* g) {
    unsigned s = (unsigned)__cvta_generic_to_shared(smem);
    asm volatile("cp.async.cg.shared.global [%0], [%1], 16;\n" :: "r"(s), "l"(g));
}
__device__ __forceinline__ float elu_f(float x) { return x > 0.f ? x : expm1f(x); }

// ---------------------------------------------------------------------------
// Kernel 1: H = X @ W, tf32 mma.sync (R6-proven, 27us). grid (2, 64).
// ---------------------------------------------------------------------------
#define K1_SMEM_BYTES ((2 * 128 * 36 + 2 * 32 * 136) * 4)

__global__ __launch_bounds__(256) void k1_gemm_xw(const float* __restrict__ X,
                                                  const float* __restrict__ W) {
    extern __shared__ float sm1[];
    float* sX = sm1;
    float* sW = sm1 + 2 * 128 * 36;

    const int tid = threadIdx.x;
    const int lane = tid & 31, warp = tid >> 5;
    const int wr = warp & 3, wc = warp >> 2;
    const int m0 = blockIdx.y * 128, n0 = blockIdx.x * 128;
    const int r0 = lane >> 2, c0 = lane & 3;
    const int sel = lane >> 3, mrow = lane & 7;
    const int lrow = ((sel & 1) << 3) + mrow, lcol = (sel >> 1) << 2;
    const unsigned sX_u = (unsigned)__cvta_generic_to_shared(sX);

    float acc[2][8][4] = {};
    float4 xv[4], wv[4];

    auto ldg_stage = [&](int k0) {
#pragma unroll
        for (int p = 0; p < 4; p++) {
            int q = tid + p * 256;
            xv[p] = *(const float4*)&X[(size_t)(m0 + (q >> 3)) * IND + k0 + ((q & 7) << 2)];
            wv[p] = *(const float4*)&W[(size_t)(k0 + (q >> 5)) * OUTD + n0 + ((q & 31) << 2)];
        }
    };
    auto sts_stage = [&](int buf) {
#pragma unroll
        for (int p = 0; p < 4; p++) {
            int q = tid + p * 256;
            float4 t = make_float4(to_tf32(xv[p].x), to_tf32(xv[p].y),
                                   to_tf32(xv[p].z), to_tf32(xv[p].w));
            *(float4*)&sX[buf * 4608 + (q >> 3) * 36 + ((q & 7) << 2)] = t;
            float4 u = make_float4(to_tf32(wv[p].x), to_tf32(wv[p].y),
                                   to_tf32(wv[p].z), to_tf32(wv[p].w));
            *(float4*)&sW[buf * 4352 + (q >> 5) * 136 + ((q & 31) << 2)] = u;
        }
    };

    ldg_stage(0);
    sts_stage(0);
    __syncthreads();

    for (int s = 0; s < 16; s++) {
        const int buf = s & 1;
        if (s < 15) ldg_stage((s + 1) * 32);
#pragma unroll
        for (int k8 = 0; k8 < 4; k8++) {
            const int kb = k8 << 3;
            unsigned afr[2][4];
#pragma unroll
            for (int mt = 0; mt < 2; mt++) {
                unsigned addr = sX_u +
                    (buf * 4608 + (wr * 32 + mt * 16 + lrow) * 36 + kb + lcol) * 4u;
                ldsm4(afr[mt], addr);
            }
            const float* wp = &sW[buf * 4352 + (kb + c0) * 136 + wc * 64 + r0];
#pragma unroll
            for (int nt = 0; nt < 8; nt++) {
                unsigned b0 = __float_as_uint(wp[nt * 8]);
                unsigned b1 = __float_as_uint(wp[4 * 136 + nt * 8]);
#pragma unroll
                for (int mt = 0; mt < 2; mt++)
                    mma_tf32(acc[mt][nt], afr[mt], b0, b1);
            }
        }
        if (s < 15) {
            __syncthreads();
            sts_stage((s + 1) & 1);
            __syncthreads();
        }
    }
#pragma unroll
    for (int mt = 0; mt < 2; mt++)
#pragma unroll
        for (int nt = 0; nt < 8; nt++) {
            const int ra = wr * 32 + mt * 16 + r0;
            const int cb = wc * 64 + nt * 8 + c0 * 2;
            *(float2*)&g_h[(size_t)(m0 + ra) * OUTD + n0 + cb] =
                make_float2(acc[mt][nt][0], acc[mt][nt][1]);
            *(float2*)&g_h[(size_t)(m0 + ra + 8) * OUTD + n0 + cb] =
                make_float2(acc[mt][nt][2], acc[mt][nt][3]);
        }
}

// ---------------------------------------------------------------------------
// Kernel 2: as/an row dots (fp32); write g_h16 (fp16, k-paired layout).
// ---------------------------------------------------------------------------
__global__ __launch_bounds__(256) void k2_attvec(const float* __restrict__ a_self,
                                                 const float* __restrict__ a_neighs) {
    const int warp = threadIdx.x >> 5, lane = threadIdx.x & 31;
    const int row = blockIdx.x * 8 + warp;
    const float4* h4 = (const float4*)&g_h[(size_t)row * OUTD];
    __half* dst = &g_h16[(size_t)(row >> 1) * 512 + (row & 1)];
    float s1 = 0.f, s2 = 0.f;
#pragma unroll
    for (int q = 0; q < 2; q++) {
        float4 v = h4[lane + 32 * q];
        float4 a = ((const float4*)a_self)[lane + 32 * q];
        float4 b = ((const float4*)a_neighs)[lane + 32 * q];
        s1 += v.x * a.x + v.y * a.y + v.z * a.z + v.w * a.w;
        s2 += v.x * b.x + v.y * b.y + v.z * b.z + v.w * b.w;
        const int c = (lane + 32 * q) * 4;
        dst[(c + 0) * 2] = __float2half_rn(v.x);
        dst[(c + 1) * 2] = __float2half_rn(v.y);
        dst[(c + 2) * 2] = __float2half_rn(v.z);
        dst[(c + 3) * 2] = __float2half_rn(v.w);
    }
#pragma unroll
    for (int off = 16; off >= 1; off >>= 1) {
        s1 += __shfl_xor_sync(0xffffffffu, s1, off);
        s2 += __shfl_xor_sync(0xffffffffu, s2, off);
    }
    if (lane == 0) { g_as[row] = s1; g_an[row] = s2; }
}

// ---------------------------------------------------------------------------
// Kernel 3: fused masked-exp attention GEMM, fp16 m16n8k16 fp16-acc.
// 32 rows x 256 cols per CTA, 128 k-tiles of 64 j. grid 256, 256 thr.
// smem ~76KB -> 2 CTAs/SM. (R11-proven structure, computeP at c16==3.)
// ---------------------------------------------------------------------------
#define SHU_STRIDE 260
#define SHU_BUF    (32 * SHU_STRIDE)          // u32 per buffer
#define SP_STRIDE  72                         // halves per row
#define SP_HBUF    (32 * SP_STRIDE)           // halves per buffer
#define SP_BYTE0   (2 * SHU_BUF * 4)          // 66560
#define SAS_F      ((SP_BYTE0 + 2 * SP_HBUF * 2) / 4)   // float idx 18944
#define SRS_F      (SAS_F + 32)
#define K3_SMEM_BYTES ((SRS_F + 32) * 4)      // 76032

__global__ __launch_bounds__(256, 2) void k3_attn(const float* __restrict__ Adj,
                                                  const float* __restrict__ Mg,
                                                  float* __restrict__ Out) {
    extern __shared__ float sm[];
    uint32_t* sHu = (uint32_t*)sm;
    __half*   sPh = (__half*)((char*)sm + SP_BYTE0);
    float* s_as = sm + SAS_F;
    float* s_rs = sm + SRS_F;

    const int tid = threadIdx.x;
    const int lane = tid & 31, warp = tid >> 5;
    const int rowbase = blockIdx.x * 32;
    const int r0 = lane >> 2, c0 = lane & 3;
    const int g = tid >> 3, cbase = (tid & 7) << 3;   // row g, 8 cols per thread
    const unsigned sP_u = (unsigned)__cvta_generic_to_shared(sPh);

    if (tid < 8)
        *(float4*)&s_as[tid * 4] = *(const float4*)&g_as[rowbase + tid * 4];

    auto stageH = [&](int tt) {
        const int b = tt & 1;
        const char* src = (const char*)g_h16 + (size_t)tt * 32 * 1024;
#pragma unroll
        for (int p = 0; p < 8; p++) {
            int ch = tid + p * 256;
            int pr = ch >> 6, c = ch & 63;
            cp16(&sHu[b * SHU_BUF + pr * SHU_STRIDE + c * 4],
                 src + (size_t)pr * 1024 + c * 16);
        }
        asm volatile("cp.async.commit_group;\n" ::: "memory");
    };

    float4 mreg[2], areg[2], ana, anb;
    auto ldgMA = [&](int tt) {
        const int jb = tt * JT;
        ana = *(const float4*)&g_an[jb + cbase];
        anb = *(const float4*)&g_an[jb + cbase + 4];
        size_t goff = (size_t)(rowbase + g) * NROWS + jb + cbase;
        mreg[0] = __ldg((const float4*)&Mg[goff]);
        mreg[1] = __ldg((const float4*)&Mg[goff + 4]);
        areg[0] = __ldg((const float4*)&Adj[goff]);
        areg[1] = __ldg((const float4*)&Adj[goff + 4]);
    };

    float rsum = 0.f;

    auto computeP = [&](int tt) {
        const int b = tt & 1;
        const float asr = s_as[g];
        float p[8];
#pragma unroll
        for (int hh = 0; hh < 2; hh++) {
            float4 m4 = mreg[hh], a4 = areg[hh];
            float4 an = hh ? anb : ana;
            float t0 = (asr + an.x) * m4.x; t0 = t0 > 0.f ? t0 : 0.2f * t0;
            float t1 = (asr + an.y) * m4.y; t1 = t1 > 0.f ? t1 : 0.2f * t1;
            float t2 = (asr + an.z) * m4.z; t2 = t2 > 0.f ? t2 : 0.2f * t2;
            float t3 = (asr + an.w) * m4.w; t3 = t3 > 0.f ? t3 : 0.2f * t3;
            p[hh * 4 + 0] = a4.x > 0.f ? __expf(t0) : 0.f;
            p[hh * 4 + 1] = a4.y > 0.f ? __expf(t1) : 0.f;
            p[hh * 4 + 2] = a4.z > 0.f ? __expf(t2) : 0.f;
            p[hh * 4 + 3] = a4.w > 0.f ? __expf(t3) : 0.f;
        }
        rsum += ((p[0] + p[1]) + (p[2] + p[3])) +
                ((p[4] + p[5]) + (p[6] + p[7]));
        __half2 h01 = __floats2half2_rn(p[0] * PSCALE, p[1] * PSCALE);
        __half2 h23 = __floats2half2_rn(p[2] * PSCALE, p[3] * PSCALE);
        __half2 h45 = __floats2half2_rn(p[4] * PSCALE, p[5] * PSCALE);
        __half2 h67 = __floats2half2_rn(p[6] * PSCALE, p[7] * PSCALE);
        *(uint4*)&sPh[b * SP_HBUF + g * SP_STRIDE + cbase] =
            make_uint4(*(unsigned*)&h01, *(unsigned*)&h23,
                       *(unsigned*)&h45, *(unsigned*)&h67);
    };

    float acc[2][4][4] = {};   // fp32 masters: 2 m-tiles x 4 n-tiles

    // ---- prologue ----
    stageH(0);
    ldgMA(0);
    __syncthreads();
    computeP(0);
    asm volatile("cp.async.wait_group 0;\n" ::: "memory");
    __syncthreads();

    // ---- main loop: 128 iterations ----
    for (int t = 0; t < NTILE; t++) {
        const int b = t & 1;
        const bool more = (t < NTILE - 1);
        if (more) { stageH(t + 1); ldgMA(t + 1); }

        unsigned hacc[2][4][2] = {};   // fp16 tile accumulators
        {
            const int nb = warp * 32 + r0;
#pragma unroll
            for (int c16 = 0; c16 < 4; c16++) {
                unsigned afr[2][4];
#pragma unroll
                for (int mt = 0; mt < 2; mt++) {
                    unsigned addr = sP_u +
                        (b * SP_HBUF + (mt * 16 + (lane & 15)) * SP_STRIDE +
                         c16 * 16 + (lane >> 4) * 8) * 2u;
                    ldsm4(afr[mt], addr);
                }
                const uint32_t* hp =
                    &sHu[b * SHU_BUF + (c16 * 8 + c0) * SHU_STRIDE + nb];
#pragma unroll
                for (int nt = 0; nt < 4; nt++) {
                    unsigned b0 = hp[nt * 8];
                    unsigned b1 = hp[4 * SHU_STRIDE + nt * 8];
#pragma unroll
                    for (int mt = 0; mt < 2; mt++)
                        mma_f16a(hacc[mt][nt], afr[mt], b0, b1);
                }
                if (c16 == 3 && more) computeP(t + 1);  // max LDG->use distance
            }
        }

        // promote fp16 tile accumulators into fp32 masters
#pragma unroll
        for (int mt = 0; mt < 2; mt++)
#pragma unroll
            for (int nt = 0; nt < 4; nt++) {
                float2 lo = __half22float2(*(__half2*)&hacc[mt][nt][0]);
                float2 hi = __half22float2(*(__half2*)&hacc[mt][nt][1]);
                acc[mt][nt][0] += lo.x; acc[mt][nt][1] += lo.y;
                acc[mt][nt][2] += hi.x; acc[mt][nt][3] += hi.y;
            }

        asm volatile("cp.async.wait_group 0;\n" ::: "memory");
        __syncthreads();
    }

    // ---- rowsum reduction (8 threads per row, same warp) ----
#pragma unroll
    for (int off = 4; off >= 1; off >>= 1)
        rsum += __shfl_xor_sync(0xffffffffu, rsum, off);
    if ((tid & 7) == 0) s_rs[g] = rsum;
    __syncthreads();

    // ---- epilogue: divide (undo 2^-6 scale), elu, store ----
#pragma unroll
    for (int mt = 0; mt < 2; mt++) {
        const int ra = mt * 16 + r0;
        const float ia = 64.0f / s_rs[ra];
        const float ib = 64.0f / s_rs[ra + 8];
#pragma unroll
        for (int nt = 0; nt < 4; nt++) {
            const int col = warp * 32 + nt * 8 + c0 * 2;
            float2 va = make_float2(elu_f(acc[mt][nt][0] * ia),
                                    elu_f(acc[mt][nt][1] * ia));
            float2 vb = make_float2(elu_f(acc[mt][nt][2] * ib),
                                    elu_f(acc[mt][nt][3] * ib));
            *(float2*)&Out[(size_t)(rowbase + ra) * OUTD + col] = va;
            *(float2*)&Out[(size_t)(rowbase + ra + 8) * OUTD + col] = vb;
        }
    }
}

// ---------------------------------------------------------------------------
extern "C" void kernel_launch(void* const* d_in, const int* in_sizes, int n_in,
                              void* d_out, int out_size) {
    const float* X        = (const float*)d_in[0];
    const float* Adj      = (const float*)d_in[1];
    const float* Mg       = (const float*)d_in[2];
    const float* W        = (const float*)d_in[3];
    const float* a_self   = (const float*)d_in[4];
    const float* a_neighs = (const float*)d_in[5];
    float* Out = (float*)d_out;

    cudaFuncSetAttribute(k1_gemm_xw, cudaFuncAttributeMaxDynamicSharedMemorySize,
                         K1_SMEM_BYTES);
    cudaFuncSetAttribute(k3_attn, cudaFuncAttributeMaxDynamicSharedMemorySize,
                         K3_SMEM_BYTES);

    k1_gemm_xw<<<dim3(2, 64), 256, K1_SMEM_BYTES>>>(X, W);
    k2_attvec<<<1024, 256>>>(a_self, a_neighs);
    k3_attn<<<256, 256, K3_SMEM_BYTES>>>(Adj, Mg, Out);
}

// round 16
// speedup vs baseline: 1.4425x; 1.0031x over previous
#include <cuda_runtime.h>
#include <cuda_fp16.h>
#include <cstdint>

// ---------------------------------------------------------------------------
// GAT layer (sm_100 base target — legacy mma.sync only):
//   k0a: ws = W@a_self, wn = W@a_neighs          (512-dot GEMV)
//   k0b: as = X@ws, an = X@wn                    (associativity: h@a = X@(W@a))
//   k1 : H = X @ W (tf32 mma.sync), epilogue writes g_h16 fp16 k-paired direct
//   k3 : Out = elu( (P @ H) / rowsum(P) )  via fp16 mma.sync m16n8k16
//        fp16 accumulate across 2 tiles (128 j) -> fp32 masters (R10-validated).
//        32x256 per CTA, JT=64, grid 256, 2 CTAs/SM, computeP at c16==3.
// ---------------------------------------------------------------------------

#define NROWS 8192
#define IND   512
#define OUTD  256
#define JT    64
#define NTILE (NROWS / JT)     // 128

__device__ __align__(16) __half g_h16[NROWS * OUTD];   // word[jpair*256+n] = {h[2j][n], h[2j+1][n]}
__device__ __align__(16) float  g_as [NROWS];
__device__ __align__(16) float  g_an [NROWS];
__device__ __align__(16) float  g_ws [IND];
__device__ __align__(16) float  g_wn [IND];

#define PSCALE 0.015625f   // 2^-6

// ---------------------------------------------------------------------------
__device__ __forceinline__ float to_tf32(float x) {
    unsigned r;
    asm("cvt.rna.tf32.f32 %0, %1;\n" : "=r"(r) : "f"(x));
    return __uint_as_float(r);
}
__device__ __forceinline__ void mma_tf32(float* d, const unsigned* a,
                                         unsigned b0, unsigned b1) {
    asm volatile(
        "mma.sync.aligned.m16n8k8.row.col.f32.tf32.tf32.f32 "
        "{%0,%1,%2,%3}, {%4,%5,%6,%7}, {%8,%9}, {%0,%1,%2,%3};\n"
        : "+f"(d[0]), "+f"(d[1]), "+f"(d[2]), "+f"(d[3])
        : "r"(a[0]), "r"(a[1]), "r"(a[2]), "r"(a[3]), "r"(b0), "r"(b1));
}
__device__ __forceinline__ void mma_f16a(unsigned* d, const unsigned* a,
                                         unsigned b0, unsigned b1) {
    asm volatile(
        "mma.sync.aligned.m16n8k16.row.col.f16.f16.f16.f16 "
        "{%0,%1}, {%2,%3,%4,%5}, {%6,%7}, {%0,%1};\n"
        : "+r"(d[0]), "+r"(d[1])
        : "r"(a[0]), "r"(a[1]), "r"(a[2]), "r"(a[3]), "r"(b0), "r"(b1));
}
__device__ __forceinline__ void ldsm4(unsigned* a, unsigned addr) {
    asm volatile(
        "ldmatrix.sync.aligned.m8n8.x4.shared.b16 {%0,%1,%2,%3}, [%4];\n"
        : "=r"(a[0]), "=r"(a[1]), "=r"(a[2]), "=r"(a[3]) : "r"(addr));
}
__device__ __forceinline__ void cp16(void* smem, const void* g) {
    unsigned s = (unsigned)__cvta_generic_to_shared(smem);
    asm volatile("cp.async.cg.shared.global [%0], [%1], 16;\n" :: "r"(s), "l"(g));
}
__device__ __forceinline__ float elu_f(float x) { return x > 0.f ? x : expm1f(x); }

// ---------------------------------------------------------------------------
// Kernel 0a: ws = W @ a_self, wn = W @ a_neighs. grid 64, block 256.
// ---------------------------------------------------------------------------
__global__ __launch_bounds__(256) void k0_wvec(const float* __restrict__ W,
                                               const float* __restrict__ a_self,
                                               const float* __restrict__ a_neighs) {
    const int warp = threadIdx.x >> 5, lane = threadIdx.x & 31;
    const int row = blockIdx.x * 8 + warp;
    const float4* w4 = (const float4*)&W[(size_t)row * OUTD];
    float s1 = 0.f, s2 = 0.f;
#pragma unroll
    for (int q = 0; q < 2; q++) {
        int i = lane + 32 * q;
        float4 v = w4[i];
        float4 a = ((const float4*)a_self)[i];
        float4 b = ((const float4*)a_neighs)[i];
        s1 += v.x * a.x + v.y * a.y + v.z * a.z + v.w * a.w;
        s2 += v.x * b.x + v.y * b.y + v.z * b.z + v.w * b.w;
    }
#pragma unroll
    for (int off = 16; off >= 1; off >>= 1) {
        s1 += __shfl_xor_sync(0xffffffffu, s1, off);
        s2 += __shfl_xor_sync(0xffffffffu, s2, off);
    }
    if (lane == 0) { g_ws[row] = s1; g_wn[row] = s2; }
}

// ---------------------------------------------------------------------------
// Kernel 0b: as = X @ ws, an = X @ wn. grid 1024, block 256.
// ---------------------------------------------------------------------------
__global__ __launch_bounds__(256) void k0_asan(const float* __restrict__ X) {
    const int warp = threadIdx.x >> 5, lane = threadIdx.x & 31;
    const int row = blockIdx.x * 8 + warp;
    const float4* x4 = (const float4*)&X[(size_t)row * IND];
    float s1 = 0.f, s2 = 0.f;
#pragma unroll
    for (int q = 0; q < 4; q++) {
        int i = lane + 32 * q;
        float4 v = x4[i];
        float4 a = ((const float4*)g_ws)[i];
        float4 b = ((const float4*)g_wn)[i];
        s1 += v.x * a.x + v.y * a.y + v.z * a.z + v.w * a.w;
        s2 += v.x * b.x + v.y * b.y + v.z * b.z + v.w * b.w;
    }
#pragma unroll
    for (int off = 16; off >= 1; off >>= 1) {
        s1 += __shfl_xor_sync(0xffffffffu, s1, off);
        s2 += __shfl_xor_sync(0xffffffffu, s2, off);
    }
    if (lane == 0) { g_as[row] = s1; g_an[row] = s2; }
}

// ---------------------------------------------------------------------------
// Kernel 1: H = X @ W, tf32 mma.sync; epilogue writes g_h16 directly.
// grid (2, 64), block 256.
// ---------------------------------------------------------------------------
#define K1_SMEM_BYTES ((2 * 128 * 36 + 2 * 32 * 136) * 4)

__global__ __launch_bounds__(256) void k1_gemm_xw(const float* __restrict__ X,
                                                  const float* __restrict__ W) {
    extern __shared__ float sm1[];
    float* sX = sm1;
    float* sW = sm1 + 2 * 128 * 36;

    const int tid = threadIdx.x;
    const int lane = tid & 31, warp = tid >> 5;
    const int wr = warp & 3, wc = warp >> 2;
    const int m0 = blockIdx.y * 128, n0 = blockIdx.x * 128;
    const int r0 = lane >> 2, c0 = lane & 3;
    const int sel = lane >> 3, mrow = lane & 7;
    const int lrow = ((sel & 1) << 3) + mrow, lcol = (sel >> 1) << 2;
    const unsigned sX_u = (unsigned)__cvta_generic_to_shared(sX);

    float acc[2][8][4] = {};
    float4 xv[4], wv[4];

    auto ldg_stage = [&](int k0) {
#pragma unroll
        for (int p = 0; p < 4; p++) {
            int q = tid + p * 256;
            xv[p] = *(const float4*)&X[(size_t)(m0 + (q >> 3)) * IND + k0 + ((q & 7) << 2)];
            wv[p] = *(const float4*)&W[(size_t)(k0 + (q >> 5)) * OUTD + n0 + ((q & 31) << 2)];
        }
    };
    auto sts_stage = [&](int buf) {
#pragma unroll
        for (int p = 0; p < 4; p++) {
            int q = tid + p * 256;
            float4 t = make_float4(to_tf32(xv[p].x), to_tf32(xv[p].y),
                                   to_tf32(xv[p].z), to_tf32(xv[p].w));
            *(float4*)&sX[buf * 4608 + (q >> 3) * 36 + ((q & 7) << 2)] = t;
            float4 u = make_float4(to_tf32(wv[p].x), to_tf32(wv[p].y),
                                   to_tf32(wv[p].z), to_tf32(wv[p].w));
            *(float4*)&sW[buf * 4352 + (q >> 5) * 136 + ((q & 31) << 2)] = u;
        }
    };

    ldg_stage(0);
    sts_stage(0);
    __syncthreads();

    for (int s = 0; s < 16; s++) {
        const int buf = s & 1;
        if (s < 15) ldg_stage((s + 1) * 32);
#pragma unroll
        for (int k8 = 0; k8 < 4; k8++) {
            const int kb = k8 << 3;
            unsigned afr[2][4];
#pragma unroll
            for (int mt = 0; mt < 2; mt++) {
                unsigned addr = sX_u +
                    (buf * 4608 + (wr * 32 + mt * 16 + lrow) * 36 + kb + lcol) * 4u;
                ldsm4(afr[mt], addr);
            }
            const float* wp = &sW[buf * 4352 + (kb + c0) * 136 + wc * 64 + r0];
#pragma unroll
            for (int nt = 0; nt < 8; nt++) {
                unsigned b0 = __float_as_uint(wp[nt * 8]);
                unsigned b1 = __float_as_uint(wp[4 * 136 + nt * 8]);
#pragma unroll
                for (int mt = 0; mt < 2; mt++)
                    mma_tf32(acc[mt][nt], afr[mt], b0, b1);
            }
        }
        if (s < 15) {
            __syncthreads();
            sts_stage((s + 1) & 1);
            __syncthreads();
        }
    }

    // epilogue: write fp16 k-paired layout directly
    // half index = (row>>1)*512 + col*2 + (row&1)
#pragma unroll
    for (int mt = 0; mt < 2; mt++)
#pragma unroll
        for (int nt = 0; nt < 8; nt++) {
            const int gr0 = m0 + wr * 32 + mt * 16 + r0;
            const int gr1 = gr0 + 8;
            const int cb  = n0 + wc * 64 + nt * 8 + c0 * 2;
            size_t base0 = (size_t)(gr0 >> 1) * 512 + (size_t)cb * 2 + (gr0 & 1);
            size_t base1 = (size_t)(gr1 >> 1) * 512 + (size_t)cb * 2 + (gr1 & 1);
            g_h16[base0]     = __float2half_rn(acc[mt][nt][0]);
            g_h16[base0 + 2] = __float2half_rn(acc[mt][nt][1]);
            g_h16[base1]     = __float2half_rn(acc[mt][nt][2]);
            g_h16[base1 + 2] = __float2half_rn(acc[mt][nt][3]);
        }
}

// ---------------------------------------------------------------------------
// Kernel 3: fused masked-exp attention GEMM, fp16 m16n8k16 fp16-acc.
// 32 rows x 256 cols per CTA, 128 k-tiles of 64 j. grid 256, 256 thr.
// smem ~76KB -> 2 CTAs/SM. computeP at c16==3; promote every 2 tiles.
// ---------------------------------------------------------------------------
#define SHU_STRIDE 260
#define SHU_BUF    (32 * SHU_STRIDE)          // u32 per buffer
#define SP_STRIDE  72                         // halves per row
#define SP_HBUF    (32 * SP_STRIDE)           // halves per buffer
#define SP_BYTE0   (2 * SHU_BUF * 4)          // 66560
#define SAS_F      ((SP_BYTE0 + 2 * SP_HBUF * 2) / 4)   // float idx 18944
#define SRS_F      (SAS_F + 32)
#define K3_SMEM_BYTES ((SRS_F + 32) * 4)      // 76032

__global__ __launch_bounds__(256, 2) void k3_attn(const float* __restrict__ Adj,
                                                  const float* __restrict__ Mg,
                                                  float* __restrict__ Out) {
    extern __shared__ float sm[];
    uint32_t* sHu = (uint32_t*)sm;
    __half*   sPh = (__half*)((char*)sm + SP_BYTE0);
    float* s_as = sm + SAS_F;
    float* s_rs = sm + SRS_F;

    const int tid = threadIdx.x;
    const int lane = tid & 31, warp = tid >> 5;
    const int rowbase = blockIdx.x * 32;
    const int r0 = lane >> 2, c0 = lane & 3;
    const int g = tid >> 3, cbase = (tid & 7) << 3;   // row g, 8 cols per thread
    const unsigned sP_u = (unsigned)__cvta_generic_to_shared(sPh);

    if (tid < 8)
        *(float4*)&s_as[tid * 4] = *(const float4*)&g_as[rowbase + tid * 4];

    auto stageH = [&](int tt) {
        const int b = tt & 1;
        const char* src = (const char*)g_h16 + (size_t)tt * 32 * 1024;
#pragma unroll
        for (int p = 0; p < 8; p++) {
            int ch = tid + p * 256;
            int pr = ch >> 6, c = ch & 63;
            cp16(&sHu[b * SHU_BUF + pr * SHU_STRIDE + c * 4],
                 src + (size_t)pr * 1024 + c * 16);
        }
        asm volatile("cp.async.commit_group;\n" ::: "memory");
    };

    float4 mreg[2], areg[2], ana, anb;
    auto ldgMA = [&](int tt) {
        const int jb = tt * JT;
        ana = *(const float4*)&g_an[jb + cbase];
        anb = *(const float4*)&g_an[jb + cbase + 4];
        size_t goff = (size_t)(rowbase + g) * NROWS + jb + cbase;
        mreg[0] = __ldg((const float4*)&Mg[goff]);
        mreg[1] = __ldg((const float4*)&Mg[goff + 4]);
        areg[0] = __ldg((const float4*)&Adj[goff]);
        areg[1] = __ldg((const float4*)&Adj[goff + 4]);
    };

    float rsum = 0.f;

    auto computeP = [&](int tt) {
        const int b = tt & 1;
        const float asr = s_as[g];
        float p[8];
#pragma unroll
        for (int hh = 0; hh < 2; hh++) {
            float4 m4 = mreg[hh], a4 = areg[hh];
            float4 an = hh ? anb : ana;
            float t0 = (asr + an.x) * m4.x; t0 = t0 > 0.f ? t0 : 0.2f * t0;
            float t1 = (asr + an.y) * m4.y; t1 = t1 > 0.f ? t1 : 0.2f * t1;
            float t2 = (asr + an.z) * m4.z; t2 = t2 > 0.f ? t2 : 0.2f * t2;
            float t3 = (asr + an.w) * m4.w; t3 = t3 > 0.f ? t3 : 0.2f * t3;
            p[hh * 4 + 0] = a4.x > 0.f ? __expf(t0) : 0.f;
            p[hh * 4 + 1] = a4.y > 0.f ? __expf(t1) : 0.f;
            p[hh * 4 + 2] = a4.z > 0.f ? __expf(t2) : 0.f;
            p[hh * 4 + 3] = a4.w > 0.f ? __expf(t3) : 0.f;
        }
        rsum += ((p[0] + p[1]) + (p[2] + p[3])) +
                ((p[4] + p[5]) + (p[6] + p[7]));
        __half2 h01 = __floats2half2_rn(p[0] * PSCALE, p[1] * PSCALE);
        __half2 h23 = __floats2half2_rn(p[2] * PSCALE, p[3] * PSCALE);
        __half2 h45 = __floats2half2_rn(p[4] * PSCALE, p[5] * PSCALE);
        __half2 h67 = __floats2half2_rn(p[6] * PSCALE, p[7] * PSCALE);
        *(uint4*)&sPh[b * SP_HBUF + g * SP_STRIDE + cbase] =
            make_uint4(*(unsigned*)&h01, *(unsigned*)&h23,
                       *(unsigned*)&h45, *(unsigned*)&h67);
    };

    float acc[2][4][4] = {};       // fp32 masters
    unsigned hacc[2][4][2];        // fp16 accumulators, live across 2 tiles

    // ---- prologue ----
    stageH(0);
    ldgMA(0);
    __syncthreads();
    computeP(0);
    asm volatile("cp.async.wait_group 0;\n" ::: "memory");
    __syncthreads();

    // ---- main loop: 128 iterations ----
    for (int t = 0; t < NTILE; t++) {
        const int b = t & 1;
        const bool more = (t < NTILE - 1);
        if (more) { stageH(t + 1); ldgMA(t + 1); }

        if ((t & 1) == 0) {   // start a fresh 2-tile fp16 accumulation group
#pragma unroll
            for (int mt = 0; mt < 2; mt++)
#pragma unroll
                for (int nt = 0; nt < 4; nt++) {
                    hacc[mt][nt][0] = 0u; hacc[mt][nt][1] = 0u;
                }
        }

        {
            const int nb = warp * 32 + r0;
#pragma unroll
            for (int c16 = 0; c16 < 4; c16++) {
                unsigned afr[2][4];
#pragma unroll
                for (int mt = 0; mt < 2; mt++) {
                    unsigned addr = sP_u +
                        (b * SP_HBUF + (mt * 16 + (lane & 15)) * SP_STRIDE +
                         c16 * 16 + (lane >> 4) * 8) * 2u;
                    ldsm4(afr[mt], addr);
                }
                const uint32_t* hp =
                    &sHu[b * SHU_BUF + (c16 * 8 + c0) * SHU_STRIDE + nb];
#pragma unroll
                for (int nt = 0; nt < 4; nt++) {
                    unsigned b0 = hp[nt * 8];
                    unsigned b1 = hp[4 * SHU_STRIDE + nt * 8];
#pragma unroll
                    for (int mt = 0; mt < 2; mt++)
                        mma_f16a(hacc[mt][nt], afr[mt], b0, b1);
                }
                if (c16 == 3 && more) computeP(t + 1);  // max LDG->use distance
            }
        }

        if (t & 1) {   // promote fp16 group into fp32 masters (every 2 tiles)
#pragma unroll
            for (int mt = 0; mt < 2; mt++)
#pragma unroll
                for (int nt = 0; nt < 4; nt++) {
                    float2 lo = __half22float2(*(__half2*)&hacc[mt][nt][0]);
                    float2 hi = __half22float2(*(__half2*)&hacc[mt][nt][1]);
                    acc[mt][nt][0] += lo.x; acc[mt][nt][1] += lo.y;
                    acc[mt][nt][2] += hi.x; acc[mt][nt][3] += hi.y;
                }
        }

        asm volatile("cp.async.wait_group 0;\n" ::: "memory");
        __syncthreads();
    }

    // ---- rowsum reduction (8 threads per row, same warp) ----
#pragma unroll
    for (int off = 4; off >= 1; off >>= 1)
        rsum += __shfl_xor_sync(0xffffffffu, rsum, off);
    if ((tid & 7) == 0) s_rs[g] = rsum;
    __syncthreads();

    // ---- epilogue: divide (undo 2^-6 scale), elu, store ----
#pragma unroll
    for (int mt = 0; mt < 2; mt++) {
        const int ra = mt * 16 + r0;
        const float ia = 64.0f / s_rs[ra];
        const float ib = 64.0f / s_rs[ra + 8];
#pragma unroll
        for (int nt = 0; nt < 4; nt++) {
            const int col = warp * 32 + nt * 8 + c0 * 2;
            float2 va = make_float2(elu_f(acc[mt][nt][0] * ia),
                                    elu_f(acc[mt][nt][1] * ia));
            float2 vb = make_float2(elu_f(acc[mt][nt][2] * ib),
                                    elu_f(acc[mt][nt][3] * ib));
            *(float2*)&Out[(size_t)(rowbase + ra) * OUTD + col] = va;
            *(float2*)&Out[(size_t)(rowbase + ra + 8) * OUTD + col] = vb;
        }
    }
}

// ---------------------------------------------------------------------------
extern "C" void kernel_launch(void* const* d_in, const int* in_sizes, int n_in,
                              void* d_out, int out_size) {
    const float* X        = (const float*)d_in[0];
    const float* Adj      = (const float*)d_in[1];
    const float* Mg       = (const float*)d_in[2];
    const float* W        = (const float*)d_in[3];
    const float* a_self   = (const float*)d_in[4];
    const float* a_neighs = (const float*)d_in[5];
    float* Out = (float*)d_out;

    cudaFuncSetAttribute(k1_gemm_xw, cudaFuncAttributeMaxDynamicSharedMemorySize,
                         K1_SMEM_BYTES);
    cudaFuncSetAttribute(k3_attn, cudaFuncAttributeMaxDynamicSharedMemorySize,
                         K3_SMEM_BYTES);

    k0_wvec<<<64, 256>>>(W, a_self, a_neighs);
    k0_asan<<<1024, 256>>>(X);
    k1_gemm_xw<<<dim3(2, 64), 256, K1_SMEM_BYTES>>>(X, W);
    k3_attn<<<256, 256, K3_SMEM_BYTES>>>(Adj, Mg, Out);
}

// round 17
// speedup vs baseline: 1.5849x; 1.0987x over previous
#include <cuda_runtime.h>
#include <cuda_fp16.h>
#include <cstdint>

// ---------------------------------------------------------------------------
// GAT layer (sm_100 base target — legacy mma.sync only):
//   k0a: ws = W@a_self, wn = W@a_neighs          (512-dot GEMV)
//   k0b: as = X@ws, an = X@wn                    (h@a = X@(W@a))
//   k1 : H = X @ W (tf32 mma.sync), epilogue writes g_h16 fp16 N-MAJOR:
//        half[(n*4096 + jpair)*2 + (row&1)]  (word = {h[2j][n], h[2j+1][n]})
//   k3 : Out = elu( (P @ H) / rowsum(P) )  via fp16 mma.sync m16n8k16
//        fp16 acc across 2 tiles -> fp32 masters. 32x256 per CTA, JT=64,
//        grid 256, 2 CTAs/SM. B fragments via ldmatrix.x4 from n-major smem
//        (replaces 32 scalar LDS/warp/tile). M/adj via __ldcs streaming.
// ---------------------------------------------------------------------------

#define NROWS 8192
#define IND   512
#define OUTD  256
#define JT    64
#define NTILE (NROWS / JT)     // 128

__device__ __align__(16) __half g_h16[NROWS * OUTD];   // n-major paired, see above
__device__ __align__(16) float  g_as [NROWS];
__device__ __align__(16) float  g_an [NROWS];
__device__ __align__(16) float  g_ws [IND];
__device__ __align__(16) float  g_wn [IND];

#define PSCALE 0.015625f   // 2^-6

// ---------------------------------------------------------------------------
__device__ __forceinline__ float to_tf32(float x) {
    unsigned r;
    asm("cvt.rna.tf32.f32 %0, %1;\n" : "=r"(r) : "f"(x));
    return __uint_as_float(r);
}
__device__ __forceinline__ void mma_tf32(float* d, const unsigned* a,
                                         unsigned b0, unsigned b1) {
    asm volatile(
        "mma.sync.aligned.m16n8k8.row.col.f32.tf32.tf32.f32 "
        "{%0,%1,%2,%3}, {%4,%5,%6,%7}, {%8,%9}, {%0,%1,%2,%3};\n"
        : "+f"(d[0]), "+f"(d[1]), "+f"(d[2]), "+f"(d[3])
        : "r"(a[0]), "r"(a[1]), "r"(a[2]), "r"(a[3]), "r"(b0), "r"(b1));
}
__device__ __forceinline__ void mma_f16a(unsigned* d, const unsigned* a,
                                         unsigned b0, unsigned b1) {
    asm volatile(
        "mma.sync.aligned.m16n8k16.row.col.f16.f16.f16.f16 "
        "{%0,%1}, {%2,%3,%4,%5}, {%6,%7}, {%0,%1};\n"
        : "+r"(d[0]), "+r"(d[1])
        : "r"(a[0]), "r"(a[1]), "r"(a[2]), "r"(a[3]), "r"(b0), "r"(b1));
}
__device__ __forceinline__ void ldsm4(unsigned* a, unsigned addr) {
    asm volatile(
        "ldmatrix.sync.aligned.m8n8.x4.shared.b16 {%0,%1,%2,%3}, [%4];\n"
        : "=r"(a[0]), "=r"(a[1]), "=r"(a[2]), "=r"(a[3]) : "r"(addr));
}
__device__ __forceinline__ void cp16(void* smem, const void* g) {
    unsigned s = (unsigned)__cvta_generic_to_shared(smem);
    asm volatile("cp.async.cg.shared.global [%0], [%1], 16;\n" :: "r"(s), "l"(g));
}
__device__ __forceinline__ float elu_f(float x) { return x > 0.f ? x : expm1f(x); }

// ---------------------------------------------------------------------------
// Kernel 0a: ws = W @ a_self, wn = W @ a_neighs. grid 64, block 256.
// ---------------------------------------------------------------------------
__global__ __launch_bounds__(256) void k0_wvec(const float* __restrict__ W,
                                               const float* __restrict__ a_self,
                                               const float* __restrict__ a_neighs) {
    const int warp = threadIdx.x >> 5, lane = threadIdx.x & 31;
    const int row = blockIdx.x * 8 + warp;
    const float4* w4 = (const float4*)&W[(size_t)row * OUTD];
    float s1 = 0.f, s2 = 0.f;
#pragma unroll
    for (int q = 0; q < 2; q++) {
        int i = lane + 32 * q;
        float4 v = w4[i];
        float4 a = ((const float4*)a_self)[i];
        float4 b = ((const float4*)a_neighs)[i];
        s1 += v.x * a.x + v.y * a.y + v.z * a.z + v.w * a.w;
        s2 += v.x * b.x + v.y * b.y + v.z * b.z + v.w * b.w;
    }
#pragma unroll
    for (int off = 16; off >= 1; off >>= 1) {
        s1 += __shfl_xor_sync(0xffffffffu, s1, off);
        s2 += __shfl_xor_sync(0xffffffffu, s2, off);
    }
    if (lane == 0) { g_ws[row] = s1; g_wn[row] = s2; }
}

// ---------------------------------------------------------------------------
// Kernel 0b: as = X @ ws, an = X @ wn. grid 1024, block 256.
// ---------------------------------------------------------------------------
__global__ __launch_bounds__(256) void k0_asan(const float* __restrict__ X) {
    const int warp = threadIdx.x >> 5, lane = threadIdx.x & 31;
    const int row = blockIdx.x * 8 + warp;
    const float4* x4 = (const float4*)&X[(size_t)row * IND];
    float s1 = 0.f, s2 = 0.f;
#pragma unroll
    for (int q = 0; q < 4; q++) {
        int i = lane + 32 * q;
        float4 v = x4[i];
        float4 a = ((const float4*)g_ws)[i];
        float4 b = ((const float4*)g_wn)[i];
        s1 += v.x * a.x + v.y * a.y + v.z * a.z + v.w * a.w;
        s2 += v.x * b.x + v.y * b.y + v.z * b.z + v.w * b.w;
    }
#pragma unroll
    for (int off = 16; off >= 1; off >>= 1) {
        s1 += __shfl_xor_sync(0xffffffffu, s1, off);
        s2 += __shfl_xor_sync(0xffffffffu, s2, off);
    }
    if (lane == 0) { g_as[row] = s1; g_an[row] = s2; }
}

// ---------------------------------------------------------------------------
// Kernel 1: H = X @ W, tf32 mma.sync; epilogue writes g_h16 N-MAJOR.
// grid (2, 64), block 256.
// ---------------------------------------------------------------------------
#define K1_SMEM_BYTES ((2 * 128 * 36 + 2 * 32 * 136) * 4)

__global__ __launch_bounds__(256) void k1_gemm_xw(const float* __restrict__ X,
                                                  const float* __restrict__ W) {
    extern __shared__ float sm1[];
    float* sX = sm1;
    float* sW = sm1 + 2 * 128 * 36;

    const int tid = threadIdx.x;
    const int lane = tid & 31, warp = tid >> 5;
    const int wr = warp & 3, wc = warp >> 2;
    const int m0 = blockIdx.y * 128, n0 = blockIdx.x * 128;
    const int r0 = lane >> 2, c0 = lane & 3;
    const int sel = lane >> 3, mrow = lane & 7;
    const int lrow = ((sel & 1) << 3) + mrow, lcol = (sel >> 1) << 2;
    const unsigned sX_u = (unsigned)__cvta_generic_to_shared(sX);

    float acc[2][8][4] = {};
    float4 xv[4], wv[4];

    auto ldg_stage = [&](int k0) {
#pragma unroll
        for (int p = 0; p < 4; p++) {
            int q = tid + p * 256;
            xv[p] = *(const float4*)&X[(size_t)(m0 + (q >> 3)) * IND + k0 + ((q & 7) << 2)];
            wv[p] = *(const float4*)&W[(size_t)(k0 + (q >> 5)) * OUTD + n0 + ((q & 31) << 2)];
        }
    };
    auto sts_stage = [&](int buf) {
#pragma unroll
        for (int p = 0; p < 4; p++) {
            int q = tid + p * 256;
            float4 t = make_float4(to_tf32(xv[p].x), to_tf32(xv[p].y),
                                   to_tf32(xv[p].z), to_tf32(xv[p].w));
            *(float4*)&sX[buf * 4608 + (q >> 3) * 36 + ((q & 7) << 2)] = t;
            float4 u = make_float4(to_tf32(wv[p].x), to_tf32(wv[p].y),
                                   to_tf32(wv[p].z), to_tf32(wv[p].w));
            *(float4*)&sW[buf * 4352 + (q >> 5) * 136 + ((q & 31) << 2)] = u;
        }
    };

    ldg_stage(0);
    sts_stage(0);
    __syncthreads();

    for (int s = 0; s < 16; s++) {
        const int buf = s & 1;
        if (s < 15) ldg_stage((s + 1) * 32);
#pragma unroll
        for (int k8 = 0; k8 < 4; k8++) {
            const int kb = k8 << 3;
            unsigned afr[2][4];
#pragma unroll
            for (int mt = 0; mt < 2; mt++) {
                unsigned addr = sX_u +
                    (buf * 4608 + (wr * 32 + mt * 16 + lrow) * 36 + kb + lcol) * 4u;
                ldsm4(afr[mt], addr);
            }
            const float* wp = &sW[buf * 4352 + (kb + c0) * 136 + wc * 64 + r0];
#pragma unroll
            for (int nt = 0; nt < 8; nt++) {
                unsigned b0 = __float_as_uint(wp[nt * 8]);
                unsigned b1 = __float_as_uint(wp[4 * 136 + nt * 8]);
#pragma unroll
                for (int mt = 0; mt < 2; mt++)
                    mma_tf32(acc[mt][nt], afr[mt], b0, b1);
            }
        }
        if (s < 15) {
            __syncthreads();
            sts_stage((s + 1) & 1);
            __syncthreads();
        }
    }

    // epilogue: n-major paired fp16.  half idx = n*8192 + (row>>1)*2 + (row&1)
#pragma unroll
    for (int mt = 0; mt < 2; mt++)
#pragma unroll
        for (int nt = 0; nt < 8; nt++) {
            const int gr0 = m0 + wr * 32 + mt * 16 + r0;
            const int gr1 = gr0 + 8;
            const int cb  = n0 + wc * 64 + nt * 8 + c0 * 2;
            size_t b00 = (size_t)cb * 8192 + (size_t)(gr0 >> 1) * 2 + (gr0 & 1);
            size_t b10 = (size_t)cb * 8192 + (size_t)(gr1 >> 1) * 2 + (gr1 & 1);
            g_h16[b00]        = __float2half_rn(acc[mt][nt][0]);
            g_h16[b00 + 8192] = __float2half_rn(acc[mt][nt][1]);
            g_h16[b10]        = __float2half_rn(acc[mt][nt][2]);
            g_h16[b10 + 8192] = __float2half_rn(acc[mt][nt][3]);
        }
}

// ---------------------------------------------------------------------------
// Kernel 3: fused masked-exp attention GEMM, fp16 m16n8k16 fp16-acc.
// 32 rows x 256 cols per CTA, 128 k-tiles of 64 j. grid 256, 256 thr.
// H staged n-major (stride 36 words); B frags via ldmatrix.x4.
// smem 83200 B -> 2 CTAs/SM. computeP at c16==3; promote every 2 tiles.
// ---------------------------------------------------------------------------
#define SHN_STRIDE 36
#define SHN_BUF    (256 * SHN_STRIDE)         // 9216 u32 per buffer
#define SP_STRIDE  72                         // halves per row
#define SP_HBUF    (32 * SP_STRIDE)           // halves per buffer
#define SP_BYTE0   (2 * SHN_BUF * 4)          // 73728
#define SAS_F      ((SP_BYTE0 + 2 * SP_HBUF * 2) / 4)   // 20736
#define SRS_F      (SAS_F + 32)
#define K3_SMEM_BYTES ((SRS_F + 32) * 4)      // 83200

__global__ __launch_bounds__(256, 2) void k3_attn(const float* __restrict__ Adj,
                                                  const float* __restrict__ Mg,
                                                  float* __restrict__ Out) {
    extern __shared__ float sm[];
    uint32_t* sHn = (uint32_t*)sm;
    __half*   sPh = (__half*)((char*)sm + SP_BYTE0);
    float* s_as = sm + SAS_F;
    float* s_rs = sm + SRS_F;

    const int tid = threadIdx.x;
    const int lane = tid & 31, warp = tid >> 5;
    const int rowbase = blockIdx.x * 32;
    const int r0 = lane >> 2, c0 = lane & 3;
    const int g = tid >> 3, cbase = (tid & 7) << 3;   // row g, 8 cols per thread
    const unsigned sP_u = (unsigned)__cvta_generic_to_shared(sPh);
    const unsigned sHn_u = (unsigned)__cvta_generic_to_shared(sHn);

    // B-frag ldmatrix lane addressing (n-major): lane l supplies row
    //   n = nb0 + 16q + ((l>>4)&1)*8 + (l&7), word base = c16*8 + ((l>>3)&1)*4
    const int bln  = warp * 32 + ((lane >> 4) & 1) * 8 + (lane & 7);
    const int bofs = bln * SHN_STRIDE + ((lane >> 3) & 1) * 4;

    if (tid < 8)
        *(float4*)&s_as[tid * 4] = *(const float4*)&g_as[rowbase + tid * 4];

    auto stageH = [&](int tt) {
        const int b = tt & 1;
#pragma unroll
        for (int p = 0; p < 8; p++) {
            int idx = tid + p * 256;
            int n = idx >> 3, c = idx & 7;
            cp16(&sHn[b * SHN_BUF + n * SHN_STRIDE + c * 4],
                 (const char*)g_h16 + (size_t)n * 16384 + (size_t)tt * 128 + c * 16);
        }
        asm volatile("cp.async.commit_group;\n" ::: "memory");
    };

    float4 mreg[2], areg[2], ana, anb;
    auto ldgMA = [&](int tt) {
        const int jb = tt * JT;
        ana = *(const float4*)&g_an[jb + cbase];
        anb = *(const float4*)&g_an[jb + cbase + 4];
        size_t goff = (size_t)(rowbase + g) * NROWS + jb + cbase;
        mreg[0] = __ldcs((const float4*)&Mg[goff]);
        mreg[1] = __ldcs((const float4*)&Mg[goff + 4]);
        areg[0] = __ldcs((const float4*)&Adj[goff]);
        areg[1] = __ldcs((const float4*)&Adj[goff + 4]);
    };

    float rsum = 0.f;

    auto computeP = [&](int tt) {
        const int b = tt & 1;
        const float asr = s_as[g];
        float p[8];
#pragma unroll
        for (int hh = 0; hh < 2; hh++) {
            float4 m4 = mreg[hh], a4 = areg[hh];
            float4 an = hh ? anb : ana;
            float t0 = (asr + an.x) * m4.x; t0 = t0 > 0.f ? t0 : 0.2f * t0;
            float t1 = (asr + an.y) * m4.y; t1 = t1 > 0.f ? t1 : 0.2f * t1;
            float t2 = (asr + an.z) * m4.z; t2 = t2 > 0.f ? t2 : 0.2f * t2;
            float t3 = (asr + an.w) * m4.w; t3 = t3 > 0.f ? t3 : 0.2f * t3;
            p[hh * 4 + 0] = a4.x > 0.f ? __expf(t0) : 0.f;
            p[hh * 4 + 1] = a4.y > 0.f ? __expf(t1) : 0.f;
            p[hh * 4 + 2] = a4.z > 0.f ? __expf(t2) : 0.f;
            p[hh * 4 + 3] = a4.w > 0.f ? __expf(t3) : 0.f;
        }
        rsum += ((p[0] + p[1]) + (p[2] + p[3])) +
                ((p[4] + p[5]) + (p[6] + p[7]));
        __half2 h01 = __floats2half2_rn(p[0] * PSCALE, p[1] * PSCALE);
        __half2 h23 = __floats2half2_rn(p[2] * PSCALE, p[3] * PSCALE);
        __half2 h45 = __floats2half2_rn(p[4] * PSCALE, p[5] * PSCALE);
        __half2 h67 = __floats2half2_rn(p[6] * PSCALE, p[7] * PSCALE);
        *(uint4*)&sPh[b * SP_HBUF + g * SP_STRIDE + cbase] =
            make_uint4(*(unsigned*)&h01, *(unsigned*)&h23,
                       *(unsigned*)&h45, *(unsigned*)&h67);
    };

    float acc[2][4][4] = {};       // fp32 masters
    unsigned hacc[2][4][2];        // fp16 accumulators, live across 2 tiles

    // ---- prologue ----
    stageH(0);
    ldgMA(0);
    __syncthreads();
    computeP(0);
    asm volatile("cp.async.wait_group 0;\n" ::: "memory");
    __syncthreads();

    // ---- main loop: 128 iterations ----
    for (int t = 0; t < NTILE; t++) {
        const int b = t & 1;
        const bool more = (t < NTILE - 1);
        if (more) { stageH(t + 1); ldgMA(t + 1); }

        if ((t & 1) == 0) {   // fresh 2-tile fp16 accumulation group
#pragma unroll
            for (int mt = 0; mt < 2; mt++)
#pragma unroll
                for (int nt = 0; nt < 4; nt++) {
                    hacc[mt][nt][0] = 0u; hacc[mt][nt][1] = 0u;
                }
        }

        {
#pragma unroll
            for (int c16 = 0; c16 < 4; c16++) {
                unsigned afr[2][4];
#pragma unroll
                for (int mt = 0; mt < 2; mt++) {
                    unsigned addr = sP_u +
                        (b * SP_HBUF + (mt * 16 + (lane & 15)) * SP_STRIDE +
                         c16 * 16 + (lane >> 4) * 8) * 2u;
                    ldsm4(afr[mt], addr);
                }
                unsigned bfr[2][4];   // q=0: nt 0,1 ; q=1: nt 2,3
#pragma unroll
                for (int q = 0; q < 2; q++) {
                    unsigned addr = sHn_u +
                        (b * SHN_BUF + bofs + q * (16 * SHN_STRIDE) + c16 * 8) * 4u;
                    ldsm4(bfr[q], addr);
                }
#pragma unroll
                for (int q = 0; q < 2; q++)
#pragma unroll
                    for (int s = 0; s < 2; s++)
#pragma unroll
                        for (int mt = 0; mt < 2; mt++)
                            mma_f16a(hacc[mt][2 * q + s], afr[mt],
                                     bfr[q][2 * s], bfr[q][2 * s + 1]);
                if (c16 == 3 && more) computeP(t + 1);  // max LDG->use distance
            }
        }

        if (t & 1) {   // promote fp16 group into fp32 masters (every 2 tiles)
#pragma unroll
            for (int mt = 0; mt < 2; mt++)
#pragma unroll
                for (int nt = 0; nt < 4; nt++) {
                    float2 lo = __half22float2(*(__half2*)&hacc[mt][nt][0]);
                    float2 hi = __half22float2(*(__half2*)&hacc[mt][nt][1]);
                    acc[mt][nt][0] += lo.x; acc[mt][nt][1] += lo.y;
                    acc[mt][nt][2] += hi.x; acc[mt][nt][3] += hi.y;
                }
        }

        asm volatile("cp.async.wait_group 0;\n" ::: "memory");
        __syncthreads();
    }

    // ---- rowsum reduction (8 threads per row, same warp) ----
#pragma unroll
    for (int off = 4; off >= 1; off >>= 1)
        rsum += __shfl_xor_sync(0xffffffffu, rsum, off);
    if ((tid & 7) == 0) s_rs[g] = rsum;
    __syncthreads();

    // ---- epilogue: divide (undo 2^-6 scale), elu, store ----
#pragma unroll
    for (int mt = 0; mt < 2; mt++) {
        const int ra = mt * 16 + r0;
        const float ia = 64.0f / s_rs[ra];
        const float ib = 64.0f / s_rs[ra + 8];
#pragma unroll
        for (int nt = 0; nt < 4; nt++) {
            const int col = warp * 32 + nt * 8 + c0 * 2;
            float2 va = make_float2(elu_f(acc[mt][nt][0] * ia),
                                    elu_f(acc[mt][nt][1] * ia));
            float2 vb = make_float2(elu_f(acc[mt][nt][2] * ib),
                                    elu_f(acc[mt][nt][3] * ib));
            *(float2*)&Out[(size_t)(rowbase + ra) * OUTD + col] = va;
            *(float2*)&Out[(size_t)(rowbase + ra + 8) * OUTD + col] = vb;
        }
    }
}

// ---------------------------------------------------------------------------
extern "C" void kernel_launch(void* const* d_in, const int* in_sizes, int n_in,
                              void* d_out, int out_size) {
    const float* X        = (const float*)d_in[0];
    const float* Adj      = (const float*)d_in[1];
    const float* Mg       = (const float*)d_in[2];
    const float* W        = (const float*)d_in[3];
    const float* a_self   = (const float*)d_in[4];
    const float* a_neighs = (const float*)d_in[5];
    float* Out = (float*)d_out;

    cudaFuncSetAttribute(k1_gemm_xw, cudaFuncAttributeMaxDynamicSharedMemorySize,
                         K1_SMEM_BYTES);
    cudaFuncSetAttribute(k3_attn, cudaFuncAttributeMaxDynamicSharedMemorySize,
                         K3_SMEM_BYTES);

    k0_wvec<<<64, 256>>>(W, a_self, a_neighs);
    k0_asan<<<1024, 256>>>(X);
    k1_gemm_xw<<<dim3(2, 64), 256, K1_SMEM_BYTES>>>(X, W);
    k3_attn<<<256, 256, K3_SMEM_BYTES>>>(Adj, Mg, Out);
}